// round 5
// baseline (speedup 1.0000x reference)
#include <cuda_runtime.h>
#include <math.h>

#define DD 128
#define WIN 15
#define WW (2*WIN+1)          // 31
#define RPB 8                 // output rows per block
#define HROWS (RPB + 4*WIN)   // 68 halo rows of x needed (±30)
#define DROWS (RPB + 2*WIN)   // 38 rows needing deg/dinv (±15)

__device__ __forceinline__ void stg256_cs(float* p, const float4& a, const float4& b) {
    asm volatile("st.global.cs.v8.f32 [%0], {%1,%2,%3,%4,%5,%6,%7,%8};"
                 :: "l"(p),
                    "f"(a.x), "f"(a.y), "f"(a.z), "f"(a.w),
                    "f"(b.x), "f"(b.y), "f"(b.z), "f"(b.w)
                 : "memory");
}

__global__ __launch_bounds__(256)
void fused_kernel(const float* __restrict__ x,
                  const float* __restrict__ qmask,
                  const int* __restrict__ dia_len,
                  float* __restrict__ out,
                  int B, int S, int NSPK) {
    __shared__ float sx[HROWS * DD];       // normalized x halo
    __shared__ int   sspk[HROWS];
    __shared__ float sdinv[DROWS];
    __shared__ float sa[RPB][WW];          // band values for central rows

    int b  = blockIdx.y;
    int i0 = blockIdx.x * RPB;
    int base = b * S;
    int len = dia_len[b];

    float4* sx4 = (float4*)sx;
    const float4* x4g = (const float4*)(x + (size_t)base * DD);

    // ---- Phase A: normalized rows [i0-30, i0+37] + speakers into smem ----
    {
        int sub = threadIdx.x & 7;         // 8 threads per row
#pragma unroll
        for (int pass = 0; pass < 3; pass++) {
            int r = pass * 32 + (threadIdx.x >> 3);
            if (r < HROWS) {
                int gr = i0 - 2 * WIN + r;
                float4 v[4];
                float ss = 0.f;
                if (gr >= 0 && gr < S) {
#pragma unroll
                    for (int k = 0; k < 4; k++) {
                        v[k] = x4g[(size_t)gr * (DD/4) + sub * 4 + k];
                        ss += v[k].x * v[k].x + v[k].y * v[k].y
                            + v[k].z * v[k].z + v[k].w * v[k].w;
                    }
                } else {
#pragma unroll
                    for (int k = 0; k < 4; k++) v[k] = make_float4(0.f, 0.f, 0.f, 0.f);
                }
#pragma unroll
                for (int off = 4; off; off >>= 1)
                    ss += __shfl_xor_sync(0xffffffffu, ss, off);
                float inv = 1.f / fmaxf(sqrtf(ss), 1e-8f);
#pragma unroll
                for (int k = 0; k < 4; k++) {
                    v[k].x *= inv; v[k].y *= inv; v[k].z *= inv; v[k].w *= inv;
                    sx4[r * (DD/4) + sub * 4 + k] = v[k];
                }
            }
        }
        if (threadIdx.x < HROWS) {
            int gr = i0 - 2 * WIN + threadIdx.x;
            int bi = -1;
            if (gr >= 0 && gr < S) {
                const float* q = qmask + ((size_t)gr * B + b) * NSPK;
                float best = q[0]; bi = 0;
                for (int k = 1; k < NSPK; k++) {
                    float v = q[k];
                    if (v > best) { best = v; bi = k; }   // JAX first-max
                }
            }
            sspk[threadIdx.x] = bi;
        }
    }
    __syncthreads();

    // ---- Phase B: deg/dinv for rows [i0-15, i0+22]; band a for central rows ----
    int warp = threadIdx.x >> 5;
    int lane = threadIdx.x & 31;

    for (int hr = warp; hr < DROWS; hr += 8) {
        int g = i0 - WIN + hr;             // global row
        bool central = (hr >= WIN && hr < WIN + RPB);
        float dinv = 1.f;
        if (g >= 0 && g < S && g < len) {
            int rg = hr + WIN;             // smem row of g
            int spk_g = sspk[rg];
            // same-speaker count in window
            bool p = false;
            if (lane < WW) {
                int gj = g - WIN + lane;
                p = (gj >= 0 && gj < len && sspk[hr + lane] == spk_g);
            }
            int cnt = __popc(__ballot_sync(0xffffffffu, p));

            float4 xi = sx4[rg * (DD/4) + lane];
            float deg = 0.f;
#pragma unroll
            for (int jj = 0; jj < WW; jj++) {
                int gj = g - WIN + jj;
                float a = 0.f;
                if (gj >= 0 && gj < len) {
                    float4 xj = sx4[(hr + jj) * (DD/4) + lane];
                    float dot = xi.x * xj.x + xi.y * xj.y + xi.z * xj.z + xi.w * xj.w;
#pragma unroll
                    for (int off = 16; off; off >>= 1)
                        dot += __shfl_xor_sync(0xffffffffu, dot, off);
                    float c = fminf(fmaxf(dot, -1.f), 1.f);
                    float wgt = 1.f - acosf(c) * 0.31830988618379067f;
                    bool same = (sspk[hr + jj] == spk_g);
                    a = wgt * ((cnt > 1 && same) ? 2.f : 1.f);
                    deg += a;
                }
                if (central && lane == 0) sa[hr - WIN][jj] = a;
            }
            dinv = (deg > 0.f) ? rsqrtf(deg) : 1.f;
        } else if (central) {
            if (lane < WW) sa[hr - WIN][lane] = 0.f;
        }
        if (lane == 0) sdinv[hr] = dinv;
    }
    __syncthreads();

    // ---- Phase C: stream full output rows, band patched inline ----
    int i = i0 + warp;
    if (i >= S) return;
    float di = sdinv[WIN + warp];
    float* orow = out + ((size_t)base + i) * S;
    int lo = i - WIN;

    int nchunks = S >> 8;                  // 256 floats per chunk (S multiple of 256)
    for (int chunk = 0; chunk < nchunks; chunk++) {
        int j0 = (chunk << 8) + (lane << 3);
        float4 va = make_float4(0.f, 0.f, 0.f, 0.f);
        float4 vb = make_float4(0.f, 0.f, 0.f, 0.f);
        int d0 = j0 - lo;
        if (d0 > -8 && d0 < WW) {          // segment overlaps the band
            float v[8];
#pragma unroll
            for (int e = 0; e < 8; e++) {
                int d = d0 + e, j = j0 + e;
                v[e] = (d >= 0 && d < WW && j < S)
                       ? sa[warp][d] * di * sdinv[warp + d] : 0.f;
            }
            va = make_float4(v[0], v[1], v[2], v[3]);
            vb = make_float4(v[4], v[5], v[6], v[7]);
        }
        stg256_cs(orow + j0, va, vb);
    }
}

extern "C" void kernel_launch(void* const* d_in, const int* in_sizes, int n_in,
                              void* d_out, int out_size) {
    const float* x       = (const float*)d_in[0];
    const float* qmask   = (const float*)d_in[1];
    const int*   dia_len = (const int*)d_in[2];
    float* out = (float*)d_out;

    int B = in_sizes[2];
    int S = in_sizes[0] / (B * DD);
    int NSPK = in_sizes[1] / (B * S);

    dim3 grid((S + RPB - 1) / RPB, B);
    fused_kernel<<<grid, 256>>>(x, qmask, dia_len, out, B, S, NSPK);
}

// round 7
// speedup vs baseline: 1.7943x; 1.7943x over previous
#include <cuda_runtime.h>
#include <math.h>

#define DD 128
#define WIN 15
#define WW (2*WIN+1)          // 31
#define MAXB 4
#define MAXS 4096
#define RPB 8                 // band rows per block
#define TROWS (RPB + 2*WIN)   // 38 smem rows

__device__ float g_band[(size_t)MAXB*MAXS*WW];
__device__ float g_dinv[MAXB*MAXS];

// ---------------- Kernel 1: fused norms + speakers + band + dinv ----------------
__global__ __launch_bounds__(256)
void bandprep_kernel(const float* __restrict__ x,
                     const float* __restrict__ qmask,
                     const int* __restrict__ dia_len,
                     int B, int S, int NSPK) {
    __shared__ float sx[TROWS * DD];   // normalized rows
    __shared__ int   sspk[TROWS];

    int b  = blockIdx.y;
    int i0 = blockIdx.x * RPB;
    int base = b * S;
    int len = dia_len[b];
    int gr0 = i0 - WIN;

    float4* sx4 = (float4*)sx;
    const float4* x4g = (const float4*)(x + (size_t)base * DD);

    // ---- Phase A: load rows [gr0, gr0+38), normalize, store to smem ----
    // NOTE: the shfl reduction must be warp-converged, so ALL lanes execute
    // the load/reduce path; only the smem stores are predicated on r < TROWS.
    {
        int sub = threadIdx.x & 7;     // 8 threads per row, 32 rows per pass
#pragma unroll
        for (int pass = 0; pass < 2; pass++) {
            int r = pass * 32 + (threadIdx.x >> 3);
            int gr = gr0 + r;
            bool inb = (r < TROWS) && (gr >= 0) && (gr < S);
            float4 v[4];
            float ss = 0.f;
            if (inb) {
#pragma unroll
                for (int k = 0; k < 4; k++) {
                    v[k] = x4g[(size_t)gr * (DD/4) + sub * 4 + k];
                    ss += v[k].x * v[k].x + v[k].y * v[k].y
                        + v[k].z * v[k].z + v[k].w * v[k].w;
                }
            } else {
#pragma unroll
                for (int k = 0; k < 4; k++) v[k] = make_float4(0.f, 0.f, 0.f, 0.f);
            }
            // warp-converged 8-lane group reduce
#pragma unroll
            for (int off = 4; off; off >>= 1)
                ss += __shfl_xor_sync(0xffffffffu, ss, off);
            float inv = 1.f / fmaxf(sqrtf(ss), 1e-8f);
            if (r < TROWS) {
#pragma unroll
                for (int k = 0; k < 4; k++) {
                    v[k].x *= inv; v[k].y *= inv; v[k].z *= inv; v[k].w *= inv;
                    sx4[r * (DD/4) + sub * 4 + k] = v[k];
                }
            }
        }
        if (threadIdx.x < TROWS) {
            int gr = gr0 + threadIdx.x;
            int bi = -1;
            if (gr >= 0 && gr < S) {
                const float* q = qmask + ((size_t)gr * B + b) * NSPK;
                float best = q[0]; bi = 0;
                for (int k = 1; k < NSPK; k++) {
                    float v = q[k];
                    if (v > best) { best = v; bi = k; }  // JAX first-max
                }
            }
            sspk[threadIdx.x] = bi;
        }
    }
    __syncthreads();

    // ---- Phase B: warp w handles row i = i0 + w (warp-uniform control flow) ----
    int w = threadIdx.x >> 5;
    int lane = threadIdx.x & 31;
    int i = i0 + w;
    if (i >= S) return;                // whole warp exits together
    int li = WIN + w;                  // smem row of i
    bool valid_i = (i < len);          // warp-uniform
    int spk_i = sspk[li];

    float4 xi = sx4[li * (DD/4) + lane];

    // same-speaker valid count in window via ballot (warp-converged)
    int cnt = 0;
    {
        bool p = false;
        if (lane < WW) {
            int j = i - WIN + lane;
            p = valid_i && (j >= 0 && j < len && sspk[w + lane] == spk_i);
        }
        cnt = __popc(__ballot_sync(0xffffffffu, p));
    }

    float deg = 0.f;
    float* bp = g_band + (size_t)(base + i) * WW;
#pragma unroll
    for (int jj = 0; jj < WW; jj++) {
        int j = i - WIN + jj;          // warp-uniform
        float a = 0.f;
        if (valid_i && j >= 0 && j < len) {   // warp-uniform condition
            float4 xj = sx4[(w + jj) * (DD/4) + lane];
            float dot = xi.x * xj.x + xi.y * xj.y + xi.z * xj.z + xi.w * xj.w;
#pragma unroll
            for (int off = 16; off; off >>= 1)
                dot += __shfl_xor_sync(0xffffffffu, dot, off);
            float c = fminf(fmaxf(dot, -1.f), 1.f);
            float wgt = 1.f - acosf(c) * 0.31830988618379067f;
            bool same = (sspk[w + jj] == spk_i);
            a = wgt * ((cnt > 1 && same) ? 2.f : 1.f);
            deg += a;
        }
        if (lane == jj) bp[jj] = a;
    }
    if (lane == 0)
        g_dinv[base + i] = (deg > 0.f) ? rsqrtf(deg) : 1.f;
}

// ---------------- Kernel 2: fused zero-fill + normalized band write ----------------
__global__ __launch_bounds__(256)
void fill_kernel(float* __restrict__ out, int B, int S) {
    int row = blockIdx.x;              // b*S + i
    int b = row / S, i = row % S;
    float di = g_dinv[row];
    const float* bp = g_band + (size_t)row * WW;
    float4* orow = (float4*)(out + (size_t)row * S);
    int lo = i - WIN;

    for (int c4 = threadIdx.x; c4 * 4 < S; c4 += blockDim.x) {
        int j0 = c4 * 4;
        float4 v = {0.f, 0.f, 0.f, 0.f};
        int d0 = j0 - lo;
        if (d0 > -4 && d0 < WW) {      // this float4 overlaps the band
            float* ve = &v.x;
#pragma unroll
            for (int e = 0; e < 4; e++) {
                int d = d0 + e, j = j0 + e;
                if (d >= 0 && d < WW && j < S)
                    ve[e] = bp[d] * di * g_dinv[b * S + j];
            }
        }
        __stcs(&orow[c4], v);
    }
}

extern "C" void kernel_launch(void* const* d_in, const int* in_sizes, int n_in,
                              void* d_out, int out_size) {
    const float* x       = (const float*)d_in[0];
    const float* qmask   = (const float*)d_in[1];
    const int*   dia_len = (const int*)d_in[2];
    float* out = (float*)d_out;

    int B = in_sizes[2];
    int S = in_sizes[0] / (B * DD);
    int NSPK = in_sizes[1] / (B * S);
    int n = B * S;

    dim3 bgrid((S + RPB - 1) / RPB, B);
    bandprep_kernel<<<bgrid, 256>>>(x, qmask, dia_len, B, S, NSPK);

    fill_kernel<<<n, 256>>>(out, B, S);
}